// round 7
// baseline (speedup 1.0000x reference)
#include <cuda_runtime.h>
#include <cuda_fp16.h>
#include <math.h>
#include <stdint.h>

// ---------------- problem constants ----------------
#define DM   1024
#define NH   16
#define DQ   64
#define DFF  4096
#define NL   6
#define SL   1024
#define NB   8
#define NT   (NB*SL)
#define NA   16
#define LN_EPS 1e-5f
#define DQKV 3072

// ---------------- scratch (static device memory) ----------------
__device__ float  g_h   [(size_t)NT*DM];
__device__ float  g_res [(size_t)NT*DM];
__device__ __half g_qkv16[(size_t)NT*DQKV];
__device__ __half g_h16 [(size_t)NT*DM];
__device__ __half g_ctx16[(size_t)NT*DM];
__device__ __half g_ff16[(size_t)NT*DFF];
__device__ __half g_wqkv16[(size_t)NL*DQKV*DM];
__device__ __half g_wo16 [(size_t)NL*DM*DM];
__device__ __half g_w116 [(size_t)NL*DM*DFF];
__device__ __half g_w216 [(size_t)NL*DFF*DM];
__device__ unsigned g_mbits[(size_t)NB*SL*SL/32];

// ================= PTX helpers =================
__device__ __forceinline__ uint32_t smem_u32(const void* p) {
    uint32_t a;
    asm("{ .reg .u64 t; cvta.to.shared.u64 t, %1; cvt.u32.u64 %0, t; }" : "=r"(a) : "l"(p));
    return a;
}
#define CP_ASYNC16(dst, src) \
    asm volatile("cp.async.cg.shared.global [%0], [%1], 16;" :: "r"(dst), "l"(src) : "memory")
#define CP_COMMIT() asm volatile("cp.async.commit_group;" ::: "memory")
#define CP_WAIT2()  asm volatile("cp.async.wait_group 2;" ::: "memory")
#define CP_WAIT1()  asm volatile("cp.async.wait_group 1;" ::: "memory")

__device__ __forceinline__ void ldsm4(uint32_t& r0, uint32_t& r1, uint32_t& r2, uint32_t& r3,
                                      uint32_t addr) {
    asm volatile("ldmatrix.sync.aligned.m8n8.x4.shared.b16 {%0,%1,%2,%3}, [%4];"
                 : "=r"(r0), "=r"(r1), "=r"(r2), "=r"(r3) : "r"(addr));
}
__device__ __forceinline__ void ldsm4t(uint32_t& r0, uint32_t& r1, uint32_t& r2, uint32_t& r3,
                                       uint32_t addr) {
    asm volatile("ldmatrix.sync.aligned.m8n8.x4.trans.shared.b16 {%0,%1,%2,%3}, [%4];"
                 : "=r"(r0), "=r"(r1), "=r"(r2), "=r"(r3) : "r"(addr));
}
__device__ __forceinline__ void mma16816(float* c, const uint32_t* a, const uint32_t* b) {
    asm volatile("mma.sync.aligned.m16n8k16.row.col.f32.f16.f16.f32 "
                 "{%0,%1,%2,%3}, {%4,%5,%6,%7}, {%8,%9}, {%0,%1,%2,%3};"
                 : "+f"(c[0]), "+f"(c[1]), "+f"(c[2]), "+f"(c[3])
                 : "r"(a[0]), "r"(a[1]), "r"(a[2]), "r"(a[3]), "r"(b[0]), "r"(b[1]));
}

// ================= HMMA fp16 GEMM (tile 128x256, warp 64x64) =================
// C[M,N] = A16[M,K] @ B16[N,K]^T.  BK=32, 4-stage cp.async, single sync/iter.
// MODE: 0 = f32 out (+bias if non-null), 1 = f16 relu+bias, 2 = f16 plain.
#define BKH   32
#define RSB   80
#define A_SZ  (128*RSB)            // 10240
#define B_SZ  (256*RSB)            // 20480
#define ST_SZ (A_SZ + B_SZ)        // 30720
#define NSTG  4
#define GSMEM (NSTG*ST_SZ)         // 122880

template<int MODE>
__global__ void __launch_bounds__(256, 1)
gemm16_kernel(const __half* __restrict__ A, const __half* __restrict__ B,
              const float* __restrict__ bias, float* __restrict__ C,
              __half* __restrict__ C16, int N, int K)
{
    extern __shared__ char smem[];
    uint32_t s0 = smem_u32(smem);
    int tid = threadIdx.x, wid = tid >> 5, lane = tid & 31;
    int wm = wid & 1, wn = wid >> 1;           // 2 m-warps x 4 n-warps, warp 64x64

    const __half* Ab = A + (size_t)blockIdx.y * 128 * K;
    const __half* Bb = B + (size_t)blockIdx.x * 256 * K;
    int KT = K / BKH;

    auto load_stage = [&](int kt) {
        uint32_t base = s0 + (kt & (NSTG-1)) * ST_SZ;
        #pragma unroll
        for (int j = 0; j < 2; j++) {                 // A: 512 chunks
            int idx = tid + j * 256;
            int row = idx >> 2, ch = idx & 3;
            CP_ASYNC16(base + row*RSB + ch*16, Ab + (size_t)row * K + kt * BKH + ch * 8);
        }
        #pragma unroll
        for (int j = 0; j < 4; j++) {                 // B: 1024 chunks
            int idx = tid + j * 256;
            int row = idx >> 2, ch = idx & 3;
            CP_ASYNC16(base + A_SZ + row*RSB + ch*16, Bb + (size_t)row * K + kt * BKH + ch * 8);
        }
    };

    #pragma unroll
    for (int kt = 0; kt < NSTG-1; kt++) { load_stage(kt); CP_COMMIT(); }

    float acc[4][8][4];
    #pragma unroll
    for (int mt = 0; mt < 4; mt++)
        #pragma unroll
        for (int nt = 0; nt < 8; nt++)
            #pragma unroll
            for (int r = 0; r < 4; r++) acc[mt][nt][r] = 0.f;

    int a_lm = lane & 15, a_kc = lane >> 4;
    int b_nr = (lane & 7) + ((lane >> 4) << 3);
    int b_kc = (lane >> 3) & 1;

    for (int kt = 0; kt < KT; kt++) {
        CP_WAIT2();
        __syncthreads();                       // iter kt-1 reads done; stage kt resident
        int ktn = kt + NSTG - 1;
        if (ktn < KT) load_stage(ktn);         // writes stage (kt-1)%4 — safe after sync
        CP_COMMIT();

        uint32_t aS = s0 + (kt & (NSTG-1))*ST_SZ;
        uint32_t bS = aS + A_SZ;
        #pragma unroll
        for (int ks = 0; ks < 2; ks++) {
            int kb = ks * 32 + a_kc * 16;
            uint32_t afr[4][4];
            #pragma unroll
            for (int mt = 0; mt < 4; mt++) {
                uint32_t ad = aS + (wm*64 + mt*16 + a_lm) * RSB + kb;
                ldsm4(afr[mt][0], afr[mt][1], afr[mt][2], afr[mt][3], ad);
            }
            uint32_t bfr[8][2];
            #pragma unroll
            for (int p = 0; p < 4; p++) {
                uint32_t r0, r1, r2, r3;
                uint32_t bd = bS + (wn*64 + p*16 + b_nr) * RSB + ks*32 + b_kc*16;
                ldsm4(r0, r1, r2, r3, bd);
                bfr[2*p][0] = r0; bfr[2*p][1] = r1;
                bfr[2*p+1][0] = r2; bfr[2*p+1][1] = r3;
            }
            #pragma unroll
            for (int mt = 0; mt < 4; mt++)
                #pragma unroll
                for (int nt = 0; nt < 8; nt++)
                    mma16816(acc[mt][nt], afr[mt], bfr[nt]);
        }
    }

    int mbase = blockIdx.y * 128 + wm * 64;
    int nbase = blockIdx.x * 256 + wn * 64;
    int lrow = lane >> 2, lcol = (lane & 3) * 2;
    #pragma unroll
    for (int mt = 0; mt < 4; mt++) {
        #pragma unroll
        for (int nt = 0; nt < 8; nt++) {
            int row = mbase + mt*16 + lrow;
            int col = nbase + nt*8 + lcol;
            float c0 = acc[mt][nt][0], c1 = acc[mt][nt][1];
            float c2 = acc[mt][nt][2], c3 = acc[mt][nt][3];
            if (MODE == 1) {
                float b0 = bias[col], b1 = bias[col+1];
                __half2 h0 = __floats2half2_rn(fmaxf(c0+b0, 0.f), fmaxf(c1+b1, 0.f));
                __half2 h1 = __floats2half2_rn(fmaxf(c2+b0, 0.f), fmaxf(c3+b1, 0.f));
                *(__half2*)(C16 + (size_t)row * N + col)     = h0;
                *(__half2*)(C16 + (size_t)(row+8) * N + col) = h1;
            } else if (MODE == 2) {
                *(__half2*)(C16 + (size_t)row * N + col)     = __floats2half2_rn(c0, c1);
                *(__half2*)(C16 + (size_t)(row+8) * N + col) = __floats2half2_rn(c2, c3);
            } else {
                if (bias) { float b0 = bias[col], b1 = bias[col+1];
                            c0 += b0; c1 += b1; c2 += b0; c3 += b1; }
                *(float2*)(C + (size_t)row * N + col)     = make_float2(c0, c1);
                *(float2*)(C + (size_t)(row+8) * N + col) = make_float2(c2, c3);
            }
        }
    }
}

// ================= HMMA flash attention (Br=128, Bc=64) =================
// grid (NB*NH, SL/128), block 256 (8 warps x 16 query rows), dynamic smem.
#define FRS 144
#define FQS (64*FRS)                 // 9216 per 64-row tile
#define FSMEM (6*FQS)                // Q(2) + K0 K1 + V0 V1 = 55296

__global__ void __launch_bounds__(256) flashh_kernel()
{
    extern __shared__ char smf[];
    uint32_t s0 = smem_u32(smf);
    uint32_t sQ = s0, sK0 = s0 + 2*FQS, sV0 = s0 + 4*FQS;
    int tid = threadIdx.x, w = tid >> 5, lane = tid & 31;
    int b = blockIdx.x >> 4, h = blockIdx.x & 15;
    int qt = blockIdx.y;

    const __half* qkv = g_qkv16;
    size_t qbase = ((size_t)(b*SL + qt*128))*DQKV + h*64;
    #pragma unroll
    for (int i = 0; i < 4; i++) {                   // 128 rows x 8 chunks
        int idx = tid + i*256; int row = idx >> 3, ch = idx & 7;
        CP_ASYNC16(sQ + row*FRS + ch*16, qkv + qbase + (size_t)row*DQKV + ch*8);
    }
    auto loadKV = [&](int t) {
        int st = t & 1;
        size_t kbase = ((size_t)(b*SL + t*64))*DQKV + 1024 + h*64;
        #pragma unroll
        for (int i = 0; i < 2; i++) {               // 64 rows x 8 chunks
            int idx = tid + i*256; int row = idx >> 3, ch = idx & 7;
            CP_ASYNC16(sK0 + st*FQS + row*FRS + ch*16, qkv + kbase + (size_t)row*DQKV + ch*8);
            CP_ASYNC16(sV0 + st*FQS + row*FRS + ch*16, qkv + kbase + 1024 + (size_t)row*DQKV + ch*8);
        }
    };
    loadKV(0); CP_COMMIT();

    float m0 = -1e30f, m1 = -1e30f, l0 = 0.f, l1 = 0.f;
    float o[8][4];
    #pragma unroll
    for (int nt = 0; nt < 8; nt++)
        #pragma unroll
        for (int r = 0; r < 4; r++) o[nt][r] = 0.f;

    int a_r = lane & 15, a_k = lane >> 4;
    int b_nr = (lane & 7) + ((lane >> 4) << 3);
    int b_kc = (lane >> 3) & 1;
    int lr = lane >> 2, lc = (lane & 3) * 2;
    int r0g = b*SL + qt*128 + w*16 + lr;
    uint32_t qf[4][4];

    for (int t = 0; t < SL/64; t++) {
        if (t+1 < SL/64) loadKV(t+1);
        CP_COMMIT();
        CP_WAIT1();
        __syncthreads();
        if (t == 0) {
            #pragma unroll
            for (int kc = 0; kc < 4; kc++)
                ldsm4(qf[kc][0], qf[kc][1], qf[kc][2], qf[kc][3],
                      sQ + (w*16 + a_r)*FRS + kc*32 + a_k*16);
        }
        uint32_t sK = sK0 + (t&1)*FQS, sV = sV0 + (t&1)*FQS;

        float sf[8][4];
        #pragma unroll
        for (int nt = 0; nt < 8; nt++)
            #pragma unroll
            for (int r = 0; r < 4; r++) sf[nt][r] = 0.f;
        #pragma unroll
        for (int kc = 0; kc < 4; kc++) {
            uint32_t bf[8][2];
            #pragma unroll
            for (int p = 0; p < 4; p++) {
                uint32_t r0, r1, r2, r3;
                ldsm4(r0, r1, r2, r3, sK + (p*16 + b_nr)*FRS + kc*32 + b_kc*16);
                bf[2*p][0] = r0; bf[2*p][1] = r1;
                bf[2*p+1][0] = r2; bf[2*p+1][1] = r3;
            }
            #pragma unroll
            for (int nt = 0; nt < 8; nt++)
                mma16816(sf[nt], qf[kc], bf[nt]);
        }

        unsigned mw00 = g_mbits[(size_t)r0g*32 + t*2],     mw01 = g_mbits[(size_t)r0g*32 + t*2 + 1];
        unsigned mw10 = g_mbits[(size_t)(r0g+8)*32 + t*2], mw11 = g_mbits[(size_t)(r0g+8)*32 + t*2 + 1];
        #pragma unroll
        for (int nt = 0; nt < 8; nt++) {
            #pragma unroll
            for (int j = 0; j < 2; j++) {
                int c = nt*8 + lc + j;
                unsigned w0 = (c < 32) ? mw00 : mw01;
                unsigned w1 = (c < 32) ? mw10 : mw11;
                int sh = c & 31;
                float v0 = sf[nt][j]   * 0.125f;
                float v1 = sf[nt][j+2] * 0.125f;
                sf[nt][j]   = ((w0 >> sh) & 1u) ? v0 : -1e9f;
                sf[nt][j+2] = ((w1 >> sh) & 1u) ? v1 : -1e9f;
            }
        }

        float tm0 = m0, tm1 = m1;
        #pragma unroll
        for (int nt = 0; nt < 8; nt++) {
            tm0 = fmaxf(tm0, fmaxf(sf[nt][0], sf[nt][1]));
            tm1 = fmaxf(tm1, fmaxf(sf[nt][2], sf[nt][3]));
        }
        #pragma unroll
        for (int off = 1; off <= 2; off <<= 1) {
            tm0 = fmaxf(tm0, __shfl_xor_sync(0xffffffffu, tm0, off));
            tm1 = fmaxf(tm1, __shfl_xor_sync(0xffffffffu, tm1, off));
        }
        float al0 = __expf(m0 - tm0), al1 = __expf(m1 - tm1);
        m0 = tm0; m1 = tm1;
        l0 *= al0; l1 *= al1;
        #pragma unroll
        for (int nt = 0; nt < 8; nt++) {
            o[nt][0] *= al0; o[nt][1] *= al0;
            o[nt][2] *= al1; o[nt][3] *= al1;
        }

        float ps0 = 0.f, ps1 = 0.f;
        uint32_t pa[4][4];
        #pragma unroll
        for (int nt = 0; nt < 8; nt++) {
            float p0 = __expf(sf[nt][0] - m0);
            float p1 = __expf(sf[nt][1] - m0);
            float p2 = __expf(sf[nt][2] - m1);
            float p3 = __expf(sf[nt][3] - m1);
            ps0 += p0 + p1; ps1 += p2 + p3;
            __half2 h01 = __floats2half2_rn(p0, p1);
            __half2 h23 = __floats2half2_rn(p2, p3);
            int cc = nt >> 1, hi = nt & 1;
            pa[cc][2*hi]     = *(uint32_t*)&h01;
            pa[cc][2*hi + 1] = *(uint32_t*)&h23;
        }
        #pragma unroll
        for (int off = 1; off <= 2; off <<= 1) {
            ps0 += __shfl_xor_sync(0xffffffffu, ps0, off);
            ps1 += __shfl_xor_sync(0xffffffffu, ps1, off);
        }
        l0 += ps0; l1 += ps1;

        #pragma unroll
        for (int cc = 0; cc < 4; cc++) {
            #pragma unroll
            for (int j = 0; j < 4; j++) {
                uint32_t r0, r1, r2, r3;
                uint32_t vd = sV + (cc*16 + (lane&7) + ((lane>>3)&1)*8)*FRS
                            + (j*16 + ((lane>>4)<<3))*2;
                ldsm4t(r0, r1, r2, r3, vd);
                uint32_t bfr0[2] = {r0, r1}, bfr1[2] = {r2, r3};
                mma16816(o[2*j],   pa[cc], bfr0);
                mma16816(o[2*j+1], pa[cc], bfr1);
            }
        }
        __syncthreads();
    }

    float inv0 = 1.0f / l0, inv1 = 1.0f / l1;
    __half* op0 = g_ctx16 + (size_t)r0g * DM + h*64;
    __half* op1 = g_ctx16 + (size_t)(r0g + 8) * DM + h*64;
    #pragma unroll
    for (int nt = 0; nt < 8; nt++) {
        int c = nt*8 + lc;
        *(__half2*)(op0 + c) = __floats2half2_rn(o[nt][0]*inv0, o[nt][1]*inv0);
        *(__half2*)(op1 + c) = __floats2half2_rn(o[nt][2]*inv1, o[nt][3]*inv1);
    }
}

// ================= weight transpose + fp16 convert =================
__global__ __launch_bounds__(256) void transconv_kernel(const float* __restrict__ src,
                                                        __half* __restrict__ dst,
                                                        int K, int N,
                                                        size_t dO, int nInner, size_t dI)
{
    __shared__ float t[32][33];
    int z = blockIdx.z;
    src += (size_t)z * K * N;
    dst += (size_t)(z / nInner) * dO + (size_t)(z % nInner) * dI;
    int k0 = blockIdx.y * 32, n0 = blockIdx.x * 32;
    int c = threadIdx.x & 31, r0 = threadIdx.x >> 5;
    #pragma unroll
    for (int rr = 0; rr < 32; rr += 8)
        t[r0 + rr][c] = src[(size_t)(k0 + r0 + rr) * N + n0 + c];
    __syncthreads();
    #pragma unroll
    for (int rr = 0; rr < 32; rr += 8)
        dst[(size_t)(n0 + r0 + rr) * K + k0 + c] = __float2half(t[c][r0 + rr]);
}

// ================= embedding + positional encoding =================
__global__ __launch_bounds__(256) void embed_kernel(const int* __restrict__ x,
                                                    const float* __restrict__ embed)
{
    int tok = blockIdx.x;
    int l   = tok & (SL-1);
    const float* e = embed + (size_t)x[tok] * DM;
    float*  out   = g_h   + (size_t)tok * DM;
    __half* out16 = g_h16 + (size_t)tok * DM;
    const float LOG2_10000 = 13.287712379549449f;
    for (int d = threadIdx.x; d < DM; d += 256) {
        float p = (float)(d & ~1) * (1.0f / (float)DM);
        float inv_div = exp2f(-LOG2_10000 * p);
        float ang = (float)(l + 1) * inv_div;
        float pe = (d & 1) ? cosf(ang) : sinf(ang);
        float v = e[d] * 32.0f + pe;
        out[d] = v;
        out16[d] = __float2half(v);
    }
}

// ================= mask -> bitmask =================
__global__ __launch_bounds__(256) void pack_mask_kernel(const int* __restrict__ mask)
{
    size_t w = (size_t)blockIdx.x * 256 + threadIdx.x;
    if (w >= (size_t)NB*SL*SL/32) return;
    const int* p = mask + w * 32;
    unsigned bits = 0;
    #pragma unroll
    for (int j = 0; j < 32; j++) bits |= (p[j] != 0 ? 1u : 0u) << j;
    g_mbits[w] = bits;
}

// ================= residual add + layernorm =================
__global__ __launch_bounds__(256) void add_ln_kernel(const float* x, const float* y,
                                                     const float* __restrict__ sc,
                                                     const float* __restrict__ bt,
                                                     float* out, __half* out16)
{
    int tok = blockIdx.x;
    const float* xp = x + (size_t)tok * DM;
    const float* yp = y + (size_t)tok * DM;
    float*  op   = out   + (size_t)tok * DM;
    __half* op16 = out16 + (size_t)tok * DM;
    __shared__ float red[8];

    float v[4]; float sum = 0.f;
    #pragma unroll
    for (int i = 0; i < 4; i++) {
        int d = threadIdx.x + 256*i;
        v[i] = xp[d] + yp[d];
        sum += v[i];
    }
    #pragma unroll
    for (int off = 16; off > 0; off >>= 1) sum += __shfl_xor_sync(0xffffffffu, sum, off);
    if ((threadIdx.x & 31) == 0) red[threadIdx.x >> 5] = sum;
    __syncthreads();
    float tot = 0.f;
    #pragma unroll
    for (int i = 0; i < 8; i++) tot += red[i];
    float mu = tot * (1.0f / (float)DM);

    float var = 0.f;
    #pragma unroll
    for (int i = 0; i < 4; i++) { float dl = v[i] - mu; var = fmaf(dl, dl, var); }
    __syncthreads();
    #pragma unroll
    for (int off = 16; off > 0; off >>= 1) var += __shfl_xor_sync(0xffffffffu, var, off);
    if ((threadIdx.x & 31) == 0) red[threadIdx.x >> 5] = var;
    __syncthreads();
    float vtot = 0.f;
    #pragma unroll
    for (int i = 0; i < 8; i++) vtot += red[i];
    float inv = rsqrtf(vtot * (1.0f / (float)DM) + LN_EPS);

    #pragma unroll
    for (int i = 0; i < 4; i++) {
        int d = threadIdx.x + 256*i;
        float r = (v[i] - mu) * inv * sc[d] + bt[d];
        op[d] = r;
        op16[d] = __float2half(r);
    }
}

// ================= output head =================
__global__ __launch_bounds__(512) void out_kernel(const float* __restrict__ w,
                                                  const float* __restrict__ bias,
                                                  float* __restrict__ out)
{
    int b = blockIdx.x;
    const float* hp = g_h + ((size_t)(b * SL + SL - 1)) * DM;
    __shared__ float logits[NA];
    int wp = threadIdx.x >> 5, lane = threadIdx.x & 31;
    float s = 0.f;
    for (int d = lane; d < DM; d += 32) s = fmaf(hp[d], w[d * NA + wp], s);
    #pragma unroll
    for (int off = 16; off > 0; off >>= 1) s += __shfl_xor_sync(0xffffffffu, s, off);
    if (lane == 0) logits[wp] = s + bias[wp];
    __syncthreads();
    if (threadIdx.x == 0) {
        float mx = -1e30f;
        for (int a = 0; a < NA; a++) mx = fmaxf(mx, logits[a]);
        float se = 0.f;
        for (int a = 0; a < NA; a++) se += expf(logits[a] - mx);
        float lse = mx + logf(se);
        for (int a = 0; a < NA; a++) out[b * NA + a] = logits[a] - lse;
    }
}

// ================= host launch =================
template<typename T> static T* symaddr(const void* s) { void* p = nullptr; cudaGetSymbolAddress(&p, s); return (T*)p; }

extern "C" void kernel_launch(void* const* d_in, const int* in_sizes, int n_in,
                              void* d_out, int out_size)
{
    (void)in_sizes; (void)n_in; (void)out_size;
    const int*   x     = (const int*)d_in[0];
    const int*   mask  = (const int*)d_in[1];
    const float* embed = (const float*)d_in[2];
    const float* Wq    = (const float*)d_in[3];
    const float* Wk    = (const float*)d_in[4];
    const float* Wv    = (const float*)d_in[5];
    const float* Wo_w  = (const float*)d_in[6];
    const float* Wo_b  = (const float*)d_in[7];
    const float* ln1_s = (const float*)d_in[8];
    const float* ln1_b = (const float*)d_in[9];
    const float* ff_w1 = (const float*)d_in[10];
    const float* ff_b1 = (const float*)d_in[11];
    const float* ff_w2 = (const float*)d_in[12];
    const float* ff_b2 = (const float*)d_in[13];
    const float* ln2_s = (const float*)d_in[14];
    const float* ln2_b = (const float*)d_in[15];
    const float* out_w = (const float*)d_in[16];
    const float* out_b = (const float*)d_in[17];
    float* out = (float*)d_out;

    float*  h_p    = symaddr<float>(g_h);
    float*  res_p  = symaddr<float>(g_res);
    __half* qkv_p  = symaddr<__half>(g_qkv16);
    __half* h16_p  = symaddr<__half>(g_h16);
    __half* ctx16_p= symaddr<__half>(g_ctx16);
    __half* ff16_p = symaddr<__half>(g_ff16);
    __half* wqkv_p = symaddr<__half>(g_wqkv16);
    __half* wo_p   = symaddr<__half>(g_wo16);
    __half* w1_p   = symaddr<__half>(g_w116);
    __half* w2_p   = symaddr<__half>(g_w216);

    cudaFuncSetAttribute(gemm16_kernel<0>, cudaFuncAttributeMaxDynamicSharedMemorySize, GSMEM);
    cudaFuncSetAttribute(gemm16_kernel<1>, cudaFuncAttributeMaxDynamicSharedMemorySize, GSMEM);
    cudaFuncSetAttribute(gemm16_kernel<2>, cudaFuncAttributeMaxDynamicSharedMemorySize, GSMEM);
    cudaFuncSetAttribute(flashh_kernel,    cudaFuncAttributeMaxDynamicSharedMemorySize, FSMEM);

    embed_kernel<<<NT, 256>>>(x, embed);
    pack_mask_kernel<<<((size_t)NB*SL*SL/32 + 255)/256, 256>>>(mask);

    transconv_kernel<<<dim3(2, 32, NL*NH), 256>>>(Wq, wqkv_p,                   DM, DQ, (size_t)DQKV*DM, NH, (size_t)DQ*DM);
    transconv_kernel<<<dim3(2, 32, NL*NH), 256>>>(Wk, wqkv_p + (size_t)DM*DM,   DM, DQ, (size_t)DQKV*DM, NH, (size_t)DQ*DM);
    transconv_kernel<<<dim3(2, 32, NL*NH), 256>>>(Wv, wqkv_p + (size_t)2*DM*DM, DM, DQ, (size_t)DQKV*DM, NH, (size_t)DQ*DM);
    transconv_kernel<<<dim3(32, 32, NL), 256>>>(Wo_w,  wo_p, DM, DM,  (size_t)DM*DM,  1, 0);
    transconv_kernel<<<dim3(128, 32, NL), 256>>>(ff_w1, w1_p, DM, DFF, (size_t)DM*DFF, 1, 0);
    transconv_kernel<<<dim3(32, 128, NL), 256>>>(ff_w2, w2_p, DFF, DM, (size_t)DFF*DM, 1, 0);

    dim3 gQKV(DQKV/256, NT/128);
    dim3 gD(DM/256, NT/128);
    dim3 gF(DFF/256, NT/128);

    for (int i = 0; i < NL; i++) {
        gemm16_kernel<2><<<gQKV, 256, GSMEM>>>(h16_p, wqkv_p + (size_t)i*DQKV*DM, nullptr, nullptr, qkv_p, DQKV, DM);
        flashh_kernel<<<dim3(NB*NH, SL/128), 256, FSMEM>>>();
        gemm16_kernel<0><<<gD, 256, GSMEM>>>(ctx16_p, wo_p + (size_t)i*DM*DM, Wo_b + (size_t)i*DM, res_p, nullptr, DM, DM);
        add_ln_kernel<<<NT, 256>>>(h_p, res_p, ln1_s + (size_t)i*DM, ln1_b + (size_t)i*DM, h_p, h16_p);
        gemm16_kernel<1><<<gF, 256, GSMEM>>>(h16_p, w1_p + (size_t)i*DM*DFF, ff_b1 + (size_t)i*DFF, nullptr, ff16_p, DFF, DM);
        gemm16_kernel<0><<<gD, 256, GSMEM>>>(ff16_p, w2_p + (size_t)i*DFF*DM, ff_b2 + (size_t)i*DM, res_p, nullptr, DM, DFF);
        add_ln_kernel<<<NT, 256>>>(h_p, res_p, ln2_s + (size_t)i*DM, ln2_b + (size_t)i*DM, h_p, h16_p);
    }
    out_kernel<<<NB, 512>>>(out_w, out_b, out);
}